// round 7
// baseline (speedup 1.0000x reference)
#include <cuda_runtime.h>

#define D 4096
#define NV4 (D / 4)        // 1024 float4 per row
#define THREADS 512
#define EPS 1e-6f

__global__ __launch_bounds__(THREADS) void mrmsnorm_kernel(
    const float4* __restrict__ x,
    const float4* __restrict__ scale,
    float4* __restrict__ out)
{
    __shared__ float ws[2][16][2];   // [row][warp][first/second half]

    const int t = threadIdx.x;
    const int warp = t >> 5;
    const int lane = t & 31;

    const size_t row0 = (size_t)blockIdx.x * 2;
    const float4* __restrict__ xr0 = x + row0 * NV4;
    const float4* __restrict__ xr1 = xr0 + NV4;

    // Front-issue all 4 streaming loads per thread (2 rows, 2 slices each).
    float4 a0 = __ldcs(&xr0[t]);             // row0, f4 idx t       in [0,512)
    float4 a1 = __ldcs(&xr0[t + THREADS]);   // row0, f4 idx t+512   in [512,1024)
    float4 b0 = __ldcs(&xr1[t]);             // row1 first half
    float4 b1 = __ldcs(&xr1[t + THREADS]);   // row1 second half

    float pa0 = a0.x * a0.x + a0.y * a0.y + a0.z * a0.z + a0.w * a0.w;
    float pa1 = a1.x * a1.x + a1.y * a1.y + a1.z * a1.z + a1.w * a1.w;
    float pb0 = b0.x * b0.x + b0.y * b0.y + b0.z * b0.z + b0.w * b0.w;
    float pb1 = b1.x * b1.x + b1.y * b1.y + b1.z * b1.z + b1.w * b1.w;

    #pragma unroll
    for (int o = 16; o > 0; o >>= 1) {
        pa0 += __shfl_down_sync(0xffffffffu, pa0, o);
        pa1 += __shfl_down_sync(0xffffffffu, pa1, o);
        pb0 += __shfl_down_sync(0xffffffffu, pb0, o);
        pb1 += __shfl_down_sync(0xffffffffu, pb1, o);
    }

    if (lane == 0) {
        ws[0][warp][0] = pa0;
        ws[0][warp][1] = pa1;
        ws[1][warp][0] = pb0;
        ws[1][warp][1] = pb1;
    }
    __syncthreads();   // single barrier for both rows

    // First-half warp -> segment map (f4 idx = warp*32..warp*32+31):
    //   warps 0-1  -> seg0 [0,64)
    //   warps 2-3  -> seg1 [64,128)
    //   warps 4-7  -> seg2 [128,256)
    //   warps 8-15 -> seg3 [256,512)
    // Second half (idx+512) -> seg4 [512,1024) for all warps.
    float ra_, rb_, qa_, qb_;
    #pragma unroll
    for (int r = 0; r < 2; r++) {
        float seg0 = ws[r][0][0] + ws[r][1][0];
        float seg1 = ws[r][2][0] + ws[r][3][0];
        float seg2 = ws[r][4][0] + ws[r][5][0] + ws[r][6][0] + ws[r][7][0];
        float seg3 = ws[r][8][0]  + ws[r][9][0]  + ws[r][10][0] + ws[r][11][0]
                   + ws[r][12][0] + ws[r][13][0] + ws[r][14][0] + ws[r][15][0];
        float seg4 = 0.0f;
        #pragma unroll
        for (int w = 0; w < 16; w++) seg4 += ws[r][w][1];

        float c0 = seg0;
        float c1 = c0 + seg1;
        float c2 = c1 + seg2;
        float c3 = c2 + seg3;
        float c4 = c3 + seg4;

        float r0 = rsqrtf(c0 * (1.0f / 256.0f)  + EPS);
        float r1 = rsqrtf(c1 * (1.0f / 512.0f)  + EPS);
        float r2 = rsqrtf(c2 * (1.0f / 1024.0f) + EPS);
        float r3 = rsqrtf(c3 * (1.0f / 2048.0f) + EPS);
        float r4 = rsqrtf(c4 * (1.0f / 4096.0f) + EPS);

        // warp-uniform select for first half
        float rfirst = (t < 64) ? r0 : (t < 128) ? r1 : (t < 256) ? r2 : r3;
        if (r == 0) { ra_ = rfirst; rb_ = r4; }
        else        { qa_ = rfirst; qb_ = r4; }
    }

    float4* __restrict__ or0 = out + row0 * NV4;
    float4* __restrict__ or1 = or0 + NV4;

    {
        float4 s = __ldg(&scale[t]);             // L1-resident after 1st CTA
        float4 o;
        o.x = a0.x * ra_ * s.x;  o.y = a0.y * ra_ * s.y;
        o.z = a0.z * ra_ * s.z;  o.w = a0.w * ra_ * s.w;
        __stcs(&or0[t], o);
        float4 p;
        p.x = b0.x * qa_ * s.x;  p.y = b0.y * qa_ * s.y;
        p.z = b0.z * qa_ * s.z;  p.w = b0.w * qa_ * s.w;
        __stcs(&or1[t], p);
    }
    {
        float4 s = __ldg(&scale[t + THREADS]);
        float4 o;
        o.x = a1.x * rb_ * s.x;  o.y = a1.y * rb_ * s.y;
        o.z = a1.z * rb_ * s.z;  o.w = a1.w * rb_ * s.w;
        __stcs(&or0[t + THREADS], o);
        float4 p;
        p.x = b1.x * qb_ * s.x;  p.y = b1.y * qb_ * s.y;
        p.z = b1.z * qb_ * s.z;  p.w = b1.w * qb_ * s.w;
        __stcs(&or1[t + THREADS], p);
    }
}

extern "C" void kernel_launch(void* const* d_in, const int* in_sizes, int n_in,
                              void* d_out, int out_size)
{
    const float4* x = (const float4*)d_in[0];
    const float4* scale = (const float4*)d_in[1];
    float4* out = (float4*)d_out;

    const int rows = out_size / D;   // 16384
    mrmsnorm_kernel<<<rows / 2, THREADS>>>(x, scale, out);
}

// round 8
// speedup vs baseline: 1.0644x; 1.0644x over previous
#include <cuda_runtime.h>

#define D 4096
#define NV4 (D / 4)        // 1024 float4 per row
#define THREADS 128
#define EPS 1e-6f

__global__ __launch_bounds__(THREADS) void mrmsnorm_kernel(
    const float4* __restrict__ x,
    const float4* __restrict__ scale,
    float4* __restrict__ out)
{
    __shared__ float ws[4][4];   // [warp][seg-group]

    const int t = threadIdx.x;
    const int warp = t >> 5;
    const int lane = t & 31;

    const size_t row = blockIdx.x;
    const float4* __restrict__ xr = x + row * NV4;
    float4* __restrict__ orow = out + row * NV4;

    // Front-issue all 8 streaming loads: slice j covers f4 idx [128j, 128j+128).
    float4 v0 = __ldcs(&xr[t]);
    float4 v1 = __ldcs(&xr[t + 1 * THREADS]);
    float4 v2 = __ldcs(&xr[t + 2 * THREADS]);
    float4 v3 = __ldcs(&xr[t + 3 * THREADS]);
    float4 v4 = __ldcs(&xr[t + 4 * THREADS]);
    float4 v5 = __ldcs(&xr[t + 5 * THREADS]);
    float4 v6 = __ldcs(&xr[t + 6 * THREADS]);
    float4 v7 = __ldcs(&xr[t + 7 * THREADS]);

    // Per-thread partials grouped by segment:
    //   p0: slice0 -> seg0/seg1 (split at t==64, warp-aligned)
    //   p1: slice1 -> seg2 [128,256)
    //   p2: slices2-3 -> seg3 [256,512)
    //   p3: slices4-7 -> seg4 [512,1024)
    float p0 = v0.x * v0.x + v0.y * v0.y + v0.z * v0.z + v0.w * v0.w;
    float p1 = v1.x * v1.x + v1.y * v1.y + v1.z * v1.z + v1.w * v1.w;
    float p2 = v2.x * v2.x + v2.y * v2.y + v2.z * v2.z + v2.w * v2.w
             + v3.x * v3.x + v3.y * v3.y + v3.z * v3.z + v3.w * v3.w;
    float p3 = v4.x * v4.x + v4.y * v4.y + v4.z * v4.z + v4.w * v4.w
             + v5.x * v5.x + v5.y * v5.y + v5.z * v5.z + v5.w * v5.w
             + v6.x * v6.x + v6.y * v6.y + v6.z * v6.z + v6.w * v6.w
             + v7.x * v7.x + v7.y * v7.y + v7.z * v7.z + v7.w * v7.w;

    #pragma unroll
    for (int o = 16; o > 0; o >>= 1) {
        p0 += __shfl_down_sync(0xffffffffu, p0, o);
        p1 += __shfl_down_sync(0xffffffffu, p1, o);
        p2 += __shfl_down_sync(0xffffffffu, p2, o);
        p3 += __shfl_down_sync(0xffffffffu, p3, o);
    }

    if (lane == 0) {
        ws[warp][0] = p0;
        ws[warp][1] = p1;
        ws[warp][2] = p2;
        ws[warp][3] = p3;
    }
    __syncthreads();

    // seg0 [0,64): warps 0-1 of slice0; seg1 [64,128): warps 2-3 of slice0.
    float seg0 = ws[0][0] + ws[1][0];
    float seg1 = ws[2][0] + ws[3][0];
    float seg2 = ws[0][1] + ws[1][1] + ws[2][1] + ws[3][1];
    float seg3 = ws[0][2] + ws[1][2] + ws[2][2] + ws[3][2];
    float seg4 = ws[0][3] + ws[1][3] + ws[2][3] + ws[3][3];

    float c0 = seg0;
    float c1 = c0 + seg1;
    float c2 = c1 + seg2;
    float c3 = c2 + seg3;
    float c4 = c3 + seg4;

    float r0 = rsqrtf(c0 * (1.0f / 256.0f)  + EPS);
    float r1 = rsqrtf(c1 * (1.0f / 512.0f)  + EPS);
    float r2 = rsqrtf(c2 * (1.0f / 1024.0f) + EPS);
    float r3 = rsqrtf(c3 * (1.0f / 2048.0f) + EPS);
    float r4 = rsqrtf(c4 * (1.0f / 4096.0f) + EPS);

    float r01 = (t < 64) ? r0 : r1;   // warp-uniform select for slice0

    {
        float4 s = __ldg(&scale[t]);
        float4 o;
        o.x = v0.x * r01 * s.x;  o.y = v0.y * r01 * s.y;
        o.z = v0.z * r01 * s.z;  o.w = v0.w * r01 * s.w;
        __stcs(&orow[t], o);
    }
    {
        float4 s = __ldg(&scale[t + 1 * THREADS]);
        float4 o;
        o.x = v1.x * r2 * s.x;  o.y = v1.y * r2 * s.y;
        o.z = v1.z * r2 * s.z;  o.w = v1.w * r2 * s.w;
        __stcs(&orow[t + 1 * THREADS], o);
    }
    {
        float4 s = __ldg(&scale[t + 2 * THREADS]);
        float4 o;
        o.x = v2.x * r3 * s.x;  o.y = v2.y * r3 * s.y;
        o.z = v2.z * r3 * s.z;  o.w = v2.w * r3 * s.w;
        __stcs(&orow[t + 2 * THREADS], o);
    }
    {
        float4 s = __ldg(&scale[t + 3 * THREADS]);
        float4 o;
        o.x = v3.x * r3 * s.x;  o.y = v3.y * r3 * s.y;
        o.z = v3.z * r3 * s.z;  o.w = v3.w * r3 * s.w;
        __stcs(&orow[t + 3 * THREADS], o);
    }
    {
        float4 s = __ldg(&scale[t + 4 * THREADS]);
        float4 o;
        o.x = v4.x * r4 * s.x;  o.y = v4.y * r4 * s.y;
        o.z = v4.z * r4 * s.z;  o.w = v4.w * r4 * s.w;
        __stcs(&orow[t + 4 * THREADS], o);
    }
    {
        float4 s = __ldg(&scale[t + 5 * THREADS]);
        float4 o;
        o.x = v5.x * r4 * s.x;  o.y = v5.y * r4 * s.y;
        o.z = v5.z * r4 * s.z;  o.w = v5.w * r4 * s.w;
        __stcs(&orow[t + 5 * THREADS], o);
    }
    {
        float4 s = __ldg(&scale[t + 6 * THREADS]);
        float4 o;
        o.x = v6.x * r4 * s.x;  o.y = v6.y * r4 * s.y;
        o.z = v6.z * r4 * s.z;  o.w = v6.w * r4 * s.w;
        __stcs(&orow[t + 6 * THREADS], o);
    }
    {
        float4 s = __ldg(&scale[t + 7 * THREADS]);
        float4 o;
        o.x = v7.x * r4 * s.x;  o.y = v7.y * r4 * s.y;
        o.z = v7.z * r4 * s.z;  o.w = v7.w * r4 * s.w;
        __stcs(&orow[t + 7 * THREADS], o);
    }
}

extern "C" void kernel_launch(void* const* d_in, const int* in_sizes, int n_in,
                              void* d_out, int out_size)
{
    const float4* x = (const float4*)d_in[0];
    const float4* scale = (const float4*)d_in[1];
    float4* out = (float4*)d_out;

    const int rows = out_size / D;   // 16384
    mrmsnorm_kernel<<<rows, THREADS>>>(x, scale, out);
}